// round 12
// baseline (speedup 1.0000x reference)
#include <cuda_runtime.h>

#define B_   8
#define NV_  2048
#define NF_  512
#define G_   96
#define VOX_ (G_*G_*G_)   // 884736

// ---------------- scratch (no allocation allowed) ----------------
struct Tet {
    float4 p0, p1, p2;   // plane r: (nx,ny,nz,c), lambda_r = nx*px+ny*py+nz*pz+c
    float4 w;            // per-plane -48/nz (x,y,z -> planes 0..2, w -> plane 3)
    int4   ib;           // xlo,xhi,ylo,yhi  (voxel index AABB, +1 guard)
    int2   zb;           // zlo,zhi
    int    flags;        // 0 = degenerate skip, 1 = fast path, 2 = fallback
    int    pad;
};
static __device__ Tet g_t[B_*NF_];
static __device__ int g_is32;

// ---------------- 0) output zero-fill ----------------
__global__ void zero_k(float4* __restrict__ o) {
    o[blockIdx.x * 256 + threadIdx.x] = make_float4(0.f, 0.f, 0.f, 0.f);
}

// ---------------- 1) facet dtype sniff (int64 vs silently-demoted int32) ---
__global__ void detect_k(const unsigned long long* __restrict__ f) {
    int any = 0;
    for (int idx = threadIdx.x; idx < B_*NF_*2; idx += blockDim.x)
        if (f[idx] >= (unsigned long long)NV_) any = 1;
    any = __syncthreads_or(any);
    if (threadIdx.x == 0) g_is32 = any;
}

// ---------------- 2) per-tet precompute ----------------
__device__ __forceinline__ bool ill_cond(float nx, float ny, float nz, float c) {
    float M = fmaxf(fmaxf(fabsf(nx), fabsf(ny)), fmaxf(fabsf(c), 1.0f));
    return 1e4f * fabsf(nz) < M;   // crossing-index error could exceed ~0.25 voxel
}

__global__ void prep_k(const float* __restrict__ verts, const void* __restrict__ fac) {
    int t = blockIdx.x * blockDim.x + threadIdx.x;
    if (t >= B_*NF_) return;
    int b = t >> 9;

    int i0, i1, i2, i3;
    if (g_is32) {
        const int* p = (const int*)fac + t*4;
        i0 = p[0]; i1 = p[1]; i2 = p[2]; i3 = p[3];
    } else {
        const long long* p = (const long long*)fac + t*4;
        i0 = (int)p[0]; i1 = (int)p[1]; i2 = (int)p[2]; i3 = (int)p[3];
    }

    const float* vb = verts + b * (NV_*3);
    float x0 = vb[3*i0+0], y0 = vb[3*i0+1], z0 = vb[3*i0+2];
    float x1 = vb[3*i1+0], y1 = vb[3*i1+1], z1 = vb[3*i1+2];
    float x2 = vb[3*i2+0], y2 = vb[3*i2+1], z2 = vb[3*i2+2];
    float x3 = vb[3*i3+0], y3 = vb[3*i3+1], z3 = vb[3*i3+2];

    float ca = x0-x3, cb = x1-x3, cc = x2-x3;
    float cd = y0-y3, ce = y1-y3, cf = y2-y3;
    float cg = z0-z3, ch = z1-z3, ci = z2-z3;

    // adjugate + det, uncontracted to mirror the reference
    float a00 = __fsub_rn(__fmul_rn(ce,ci), __fmul_rn(cf,ch));
    float a01 = __fsub_rn(__fmul_rn(cc,ch), __fmul_rn(cb,ci));
    float a02 = __fsub_rn(__fmul_rn(cb,cf), __fmul_rn(cc,ce));
    float a10 = __fsub_rn(__fmul_rn(cf,cg), __fmul_rn(cd,ci));
    float a11 = __fsub_rn(__fmul_rn(ca,ci), __fmul_rn(cc,cg));
    float a12 = __fsub_rn(__fmul_rn(cc,cd), __fmul_rn(ca,cf));
    float a20 = __fsub_rn(__fmul_rn(cd,ch), __fmul_rn(ce,cg));
    float a21 = __fsub_rn(__fmul_rn(cb,cg), __fmul_rn(ca,ch));
    float a22 = __fsub_rn(__fmul_rn(ca,ce), __fmul_rn(cb,cd));
    float u   = __fsub_rn(__fmul_rn(cd,ci), __fmul_rn(cf,cg));
    float det = __fadd_rn(__fsub_rn(__fmul_rn(ca,a00), __fmul_rn(cb,u)),
                          __fmul_rn(cc,a20));

    double inv = 1.0 / (double)det;
    float4 p0, p1, p2;
    p0.x = (float)((double)a00*inv); p0.y = (float)((double)a01*inv); p0.z = (float)((double)a02*inv);
    p1.x = (float)((double)a10*inv); p1.y = (float)((double)a11*inv); p1.z = (float)((double)a12*inv);
    p2.x = (float)((double)a20*inv); p2.y = (float)((double)a21*inv); p2.z = (float)((double)a22*inv);
    p0.w = (float)(-((double)a00*x3 + (double)a01*y3 + (double)a02*z3) * inv);
    p1.w = (float)(-((double)a10*x3 + (double)a11*y3 + (double)a12*z3) * inv);
    p2.w = (float)(-((double)a20*x3 + (double)a21*y3 + (double)a22*z3) * inv);

    // plane 3 (l3 = 1 - l0 - l1 - l2) linear-form coefficients (approx use only)
    float n3x = -(p0.x + p1.x + p2.x);
    float n3y = -(p0.y + p1.y + p2.y);
    float n3z = -(p0.z + p1.z + p2.z);
    float c3  = 1.0f - (p0.w + p1.w + p2.w);

    const float M = 1e-5f;  // conservative AABB margin
    float bxmin = fminf(fminf(x0,x1), fminf(x2,x3)) - M;
    float bxmax = fmaxf(fmaxf(x0,x1), fmaxf(x2,x3)) + M;
    float bymin = fminf(fminf(y0,y1), fminf(y2,y3)) - M;
    float bymax = fmaxf(fmaxf(y0,y1), fmaxf(y2,y3)) + M;
    float bzmin = fminf(fminf(z0,z1), fminf(z2,z3)) - M;
    float bzmax = fmaxf(fmaxf(z0,z1), fmaxf(z2,z3)) + M;

    Tet T;
    T.ib.x = max(0,  (int)ceilf ((96.f*bxmin + 95.f)*0.5f) - 1);
    T.ib.y = min(95, (int)floorf((96.f*bxmax + 95.f)*0.5f) + 1);
    T.ib.z = max(0,  (int)ceilf ((96.f*bymin + 95.f)*0.5f) - 1);
    T.ib.w = min(95, (int)floorf((96.f*bymax + 95.f)*0.5f) + 1);
    T.zb.x = max(0,  (int)ceilf ((96.f*bzmin + 95.f)*0.5f) - 1);
    T.zb.y = min(95, (int)floorf((96.f*bzmax + 95.f)*0.5f) + 1);

    int flags;
    if (!(fabsf(det) > 0.0f)) flags = 0;                 // degenerate -> never inside
    else if (ill_cond(p0.x,p0.y,p0.z,p0.w) || ill_cond(p1.x,p1.y,p1.z,p1.w) ||
             ill_cond(p2.x,p2.y,p2.z,p2.w) || ill_cond(n3x,n3y,n3z,c3))
        flags = 2;                                       // rare: exact chunked path
    else flags = 1;

    float4 w;
    w.x = (float)(-48.0 / (double)p0.z);
    w.y = (float)(-48.0 / (double)p1.z);
    w.z = (float)(-48.0 / (double)p2.z);
    w.w = (float)(-48.0 / (double)n3z);

    T.p0 = p0; T.p1 = p1; T.p2 = p2; T.w = w; T.flags = flags; T.pad = 0;
    g_t[t] = T;
}

// ---------------- 3) per-tet rasterize: exact z-run per column ------------
// block = one tet; 8 warps stride x rows; lanes = 32 y-columns per chunk.
__global__ __launch_bounds__(256) void vox_k(float* __restrict__ out) {
    __shared__ float s_p[G_];
    if (threadIdx.x < G_)
        s_p[threadIdx.x] = __fdiv_rn((float)(2*(int)threadIdx.x - 95), 96.0f);
    __syncthreads();

    const Tet& T = g_t[blockIdx.y * NF_ + blockIdx.x];
    int flags = T.flags;
    if (flags == 0) return;

    int warp = threadIdx.x >> 5, lane = threadIdx.x & 31;
    float4 P0 = T.p0, P1 = T.p1, P2 = T.p2;
    int4 ib = T.ib; int2 zb = T.zb;
    float* outb = out + (size_t)blockIdx.y * VOX_;

    if (flags == 2) {
        // -------- fallback: exact chunked test over whole box (R4 path) -----
        int nzc = ((zb.y - zb.x) >> 5) + 1;
        float pzc[3];
        #pragma unroll
        for (int k = 0; k < 3; ++k)
            pzc[k] = s_p[min(zb.x + k*32 + lane, 95)];
        for (int xi = ib.x; xi <= ib.y; ++xi) {
            float px  = s_p[xi];
            float e0x = fmaf(P0.x, px, P0.w);
            float e1x = fmaf(P1.x, px, P1.w);
            float e2x = fmaf(P2.x, px, P2.w);
            int rowx = xi * G_;
            for (int yi = ib.z + warp; yi <= ib.w; yi += 8) {
                float py = s_p[yi];
                float e0 = fmaf(P0.y, py, e0x);
                float e1 = fmaf(P1.y, py, e1x);
                float e2 = fmaf(P2.y, py, e2x);
                float* col = outb + (size_t)(rowx + yi) * G_ + zb.x + lane;
                #pragma unroll
                for (int k = 0; k < 3; ++k) {
                    if (k >= nzc) break;
                    float l0 = fmaf(P0.z, pzc[k], e0);
                    float l1 = fmaf(P1.z, pzc[k], e1);
                    float l2 = fmaf(P2.z, pzc[k], e2);
                    float l3 = 1.0f - (l0 + l1 + l2);
                    float m = fminf(fminf(l0, l1), fminf(l2, l3));
                    int z = zb.x + k*32 + lane;
                    if ((m >= 0.0f) && (z <= zb.y)) col[k*32] = 1.0f;
                }
            }
        }
        return;
    }

    // -------- fast path --------
    float4 W = T.w;
    bool s0 = P0.z > 0.0f, s1 = P1.z > 0.0f, s2 = P2.z > 0.0f;
    bool s3 = (-(P0.z + P1.z + P2.z)) > 0.0f;   // sign of n3z

    for (int xi = ib.x + warp; xi <= ib.y; xi += 8) {
        float px  = s_p[xi];
        float ex0 = fmaf(P0.x, px, P0.w);
        float ex1 = fmaf(P1.x, px, P1.w);
        float ex2 = fmaf(P2.x, px, P2.w);

        for (int ybase = ib.z; ybase <= ib.w; ybase += 32) {
            int  y   = ybase + lane;
            bool yok = (y <= ib.w);
            float py = s_p[y > 95 ? 95 : y];
            float e0 = fmaf(P0.y, py, ex0);
            float e1 = fmaf(P1.y, py, ex1);
            float e2 = fmaf(P2.y, py, ex2);
            float e3 = 1.0f - (e0 + e1 + e2);   // approx linear const, plane 3

            // approximate crossing positions in z-index space
            float i0 = fmaf(e0, W.x, 47.5f);
            float i1 = fmaf(e1, W.y, 47.5f);
            float i2 = fmaf(e2, W.z, 47.5f);
            float i3 = fmaf(e3, W.w, 47.5f);
            float lo = fmaxf(fmaxf(s0 ? i0 : -1e30f, s1 ? i1 : -1e30f),
                             fmaxf(s2 ? i2 : -1e30f, s3 ? i3 : -1e30f));
            float hi = fminf(fminf(s0 ? 1e30f : i0, s1 ? 1e30f : i1),
                             fminf(s2 ? 1e30f : i2, s3 ? 1e30f : i3));
            int sA = __float2int_ru(lo);
            int eA = __float2int_rd(hi);

            int st = 96, en = 0;                // empty encoding: st > en
            bool act = yok && (sA <= eA + 2);   // crossing err < 0.25 => safe skip
            if (__any_sync(0xffffffffu, act)) {
                // exact membership test — IDENTICAL FP chain to the passing kernel
                auto TST = [&](int z) -> bool {
                    float pz = s_p[z];
                    float l0 = fmaf(P0.z, pz, e0);
                    float l1 = fmaf(P1.z, pz, e1);
                    float l2 = fmaf(P2.z, pz, e2);
                    float l3 = 1.0f - (l0 + l1 + l2);
                    return fminf(fminf(l0, l1), fminf(l2, l3)) >= 0.0f;
                };
                if (act) {
                    int cs0 = min(max(sA-1, 0), 95);
                    int cs1 = min(max(sA  , 0), 95);
                    int cs2 = min(max(sA+1, 0), 95);
                    bool t0 = TST(cs0), t1 = TST(cs1), t2 = TST(cs2);
                    int stc = t0 ? cs0 : (t1 ? cs1 : (t2 ? cs2 : 96));
                    int ce0 = min(max(eA+1, 0), 95);
                    int ce1 = min(max(eA  , 0), 95);
                    int ce2 = min(max(eA-1, 0), 95);
                    bool u0 = TST(ce0), u1 = TST(ce1), u2 = TST(ce2);
                    int enc = u0 ? ce0 : (u1 ? ce1 : (u2 ? ce2 : -1));
                    if (stc <= enc) { st = stc; en = enc; }
                }
            }

            // ---- phase 3: ffs-compacted fill over nonempty columns only.
            // Per column: one address reg, 3 predicated stores at +0/+128/+256B
            // (len <= 95 always, so 3 chunks cover every possible run).
            unsigned m1 = __ballot_sync(0xffffffffu, st <= en);
            if (m1) {
                int pk = (st << 8) | en;         // st in [0,96], en in [0,95]
                float* base = outb + (size_t)(xi * G_ + ybase) * G_;
                while (m1) {
                    int j = __ffs(m1) - 1; m1 &= m1 - 1;
                    int pkj = __shfl_sync(0xffffffffu, pk, j);
                    int bs = pkj >> 8, be = pkj & 255;
                    float* col = base + j * G_ + bs + lane;
                    int zrel = lane - (be - bs);           // <=0 while in run
                    if (zrel      <= 0) col[0]  = 1.0f;
                    if (zrel + 32 <= 0) col[32] = 1.0f;
                    if (zrel + 64 <= 0) col[64] = 1.0f;
                }
            }
        }
    }
}

// ---------------- launch ----------------
extern "C" void kernel_launch(void* const* d_in, const int* in_sizes, int n_in,
                              void* d_out, int out_size) {
    const float* verts = (const float*)d_in[0];
    const void*  fac   = d_in[1];
    (void)in_sizes; (void)n_in; (void)out_size;

    zero_k  <<<(B_*VOX_/4) / 256, 256>>>((float4*)d_out);
    detect_k<<<1, 256>>>((const unsigned long long*)fac);
    prep_k  <<<(B_*NF_ + 255) / 256, 256>>>(verts, fac);
    vox_k   <<<dim3(NF_, B_), 256>>>((float*)d_out);
}

// round 13
// speedup vs baseline: 2.5025x; 2.5025x over previous
#include <cuda_runtime.h>

#define B_   8
#define NV_  2048
#define NF_  512
#define G_   96
#define VOX_ (G_*G_*G_)   // 884736

// ---------------- scratch (no allocation allowed) ----------------
struct Tet {
    float4 p0, p1, p2;   // plane r: (nx,ny,nz,c), lambda_r = nx*px+ny*py+nz*pz+c
    float4 w;            // per-plane -48/nz (x,y,z -> planes 0..2, w -> plane 3)
    int4   ib;           // xlo,xhi,ylo,yhi  (voxel index AABB, +1 guard)
    int2   zb;           // zlo,zhi
    int    flags;        // 0 = degenerate skip, 1 = fast path, 2 = fallback
    int    pad;
};
static __device__ Tet g_t[B_*NF_];
static __device__ int g_is32;

// ---------------- 0) output zero-fill ----------------
__global__ void zero_k(float4* __restrict__ o) {
    o[blockIdx.x * 256 + threadIdx.x] = make_float4(0.f, 0.f, 0.f, 0.f);
}

// ---------------- 1) facet dtype sniff (int64 vs silently-demoted int32) ---
__global__ void detect_k(const unsigned long long* __restrict__ f) {
    int any = 0;
    for (int idx = threadIdx.x; idx < B_*NF_*2; idx += blockDim.x)
        if (f[idx] >= (unsigned long long)NV_) any = 1;
    any = __syncthreads_or(any);
    if (threadIdx.x == 0) g_is32 = any;
}

// ---------------- 2) per-tet precompute ----------------
__device__ __forceinline__ bool ill_cond(float nx, float ny, float nz, float c) {
    float M = fmaxf(fmaxf(fabsf(nx), fabsf(ny)), fmaxf(fabsf(c), 1.0f));
    return 1e4f * fabsf(nz) < M;   // crossing-index error could exceed ~0.25 voxel
}

__global__ void prep_k(const float* __restrict__ verts, const void* __restrict__ fac) {
    int t = blockIdx.x * blockDim.x + threadIdx.x;
    if (t >= B_*NF_) return;
    int b = t >> 9;

    int i0, i1, i2, i3;
    if (g_is32) {
        const int* p = (const int*)fac + t*4;
        i0 = p[0]; i1 = p[1]; i2 = p[2]; i3 = p[3];
    } else {
        const long long* p = (const long long*)fac + t*4;
        i0 = (int)p[0]; i1 = (int)p[1]; i2 = (int)p[2]; i3 = (int)p[3];
    }

    const float* vb = verts + b * (NV_*3);
    float x0 = vb[3*i0+0], y0 = vb[3*i0+1], z0 = vb[3*i0+2];
    float x1 = vb[3*i1+0], y1 = vb[3*i1+1], z1 = vb[3*i1+2];
    float x2 = vb[3*i2+0], y2 = vb[3*i2+1], z2 = vb[3*i2+2];
    float x3 = vb[3*i3+0], y3 = vb[3*i3+1], z3 = vb[3*i3+2];

    float ca = x0-x3, cb = x1-x3, cc = x2-x3;
    float cd = y0-y3, ce = y1-y3, cf = y2-y3;
    float cg = z0-z3, ch = z1-z3, ci = z2-z3;

    // adjugate + det, uncontracted to mirror the reference
    float a00 = __fsub_rn(__fmul_rn(ce,ci), __fmul_rn(cf,ch));
    float a01 = __fsub_rn(__fmul_rn(cc,ch), __fmul_rn(cb,ci));
    float a02 = __fsub_rn(__fmul_rn(cb,cf), __fmul_rn(cc,ce));
    float a10 = __fsub_rn(__fmul_rn(cf,cg), __fmul_rn(cd,ci));
    float a11 = __fsub_rn(__fmul_rn(ca,ci), __fmul_rn(cc,cg));
    float a12 = __fsub_rn(__fmul_rn(cc,cd), __fmul_rn(ca,cf));
    float a20 = __fsub_rn(__fmul_rn(cd,ch), __fmul_rn(ce,cg));
    float a21 = __fsub_rn(__fmul_rn(cb,cg), __fmul_rn(ca,ch));
    float a22 = __fsub_rn(__fmul_rn(ca,ce), __fmul_rn(cb,cd));
    float u   = __fsub_rn(__fmul_rn(cd,ci), __fmul_rn(cf,cg));
    float det = __fadd_rn(__fsub_rn(__fmul_rn(ca,a00), __fmul_rn(cb,u)),
                          __fmul_rn(cc,a20));

    double inv = 1.0 / (double)det;
    float4 p0, p1, p2;
    p0.x = (float)((double)a00*inv); p0.y = (float)((double)a01*inv); p0.z = (float)((double)a02*inv);
    p1.x = (float)((double)a10*inv); p1.y = (float)((double)a11*inv); p1.z = (float)((double)a12*inv);
    p2.x = (float)((double)a20*inv); p2.y = (float)((double)a21*inv); p2.z = (float)((double)a22*inv);
    p0.w = (float)(-((double)a00*x3 + (double)a01*y3 + (double)a02*z3) * inv);
    p1.w = (float)(-((double)a10*x3 + (double)a11*y3 + (double)a12*z3) * inv);
    p2.w = (float)(-((double)a20*x3 + (double)a21*y3 + (double)a22*z3) * inv);

    // plane 3 (l3 = 1 - l0 - l1 - l2) linear-form coefficients (approx use only)
    float n3x = -(p0.x + p1.x + p2.x);
    float n3y = -(p0.y + p1.y + p2.y);
    float n3z = -(p0.z + p1.z + p2.z);
    float c3  = 1.0f - (p0.w + p1.w + p2.w);

    const float M = 1e-5f;  // conservative AABB margin
    float bxmin = fminf(fminf(x0,x1), fminf(x2,x3)) - M;
    float bxmax = fmaxf(fmaxf(x0,x1), fmaxf(x2,x3)) + M;
    float bymin = fminf(fminf(y0,y1), fminf(y2,y3)) - M;
    float bymax = fmaxf(fmaxf(y0,y1), fmaxf(y2,y3)) + M;
    float bzmin = fminf(fminf(z0,z1), fminf(z2,z3)) - M;
    float bzmax = fmaxf(fmaxf(z0,z1), fmaxf(z2,z3)) + M;

    Tet T;
    T.ib.x = max(0,  (int)ceilf ((96.f*bxmin + 95.f)*0.5f) - 1);
    T.ib.y = min(95, (int)floorf((96.f*bxmax + 95.f)*0.5f) + 1);
    T.ib.z = max(0,  (int)ceilf ((96.f*bymin + 95.f)*0.5f) - 1);
    T.ib.w = min(95, (int)floorf((96.f*bymax + 95.f)*0.5f) + 1);
    T.zb.x = max(0,  (int)ceilf ((96.f*bzmin + 95.f)*0.5f) - 1);
    T.zb.y = min(95, (int)floorf((96.f*bzmax + 95.f)*0.5f) + 1);

    int flags;
    if (!(fabsf(det) > 0.0f)) flags = 0;                 // degenerate -> never inside
    else if (ill_cond(p0.x,p0.y,p0.z,p0.w) || ill_cond(p1.x,p1.y,p1.z,p1.w) ||
             ill_cond(p2.x,p2.y,p2.z,p2.w) || ill_cond(n3x,n3y,n3z,c3))
        flags = 2;                                       // rare: exact chunked path
    else flags = 1;

    float4 w;
    w.x = (float)(-48.0 / (double)p0.z);
    w.y = (float)(-48.0 / (double)p1.z);
    w.z = (float)(-48.0 / (double)p2.z);
    w.w = (float)(-48.0 / (double)n3z);

    T.p0 = p0; T.p1 = p1; T.p2 = p2; T.w = w; T.flags = flags; T.pad = 0;
    g_t[t] = T;
}

// ---------------- 3) per-tet rasterize: exact z-run per column ------------
// block = one tet; 16 warps stride x rows; lanes = 32 y-columns per chunk.
__global__ __launch_bounds__(512) void vox_k(float* __restrict__ out) {
    __shared__ float s_p[G_];
    if (threadIdx.x < G_)
        s_p[threadIdx.x] = __fdiv_rn((float)(2*(int)threadIdx.x - 95), 96.0f);
    __syncthreads();

    const Tet& T = g_t[blockIdx.y * NF_ + blockIdx.x];
    int flags = T.flags;
    if (flags == 0) return;

    int warp = threadIdx.x >> 5, lane = threadIdx.x & 31;
    float4 P0 = T.p0, P1 = T.p1, P2 = T.p2;
    int4 ib = T.ib; int2 zb = T.zb;
    float* outb = out + (size_t)blockIdx.y * VOX_;

    if (flags == 2) {
        // -------- fallback: exact chunked test over whole box (R4 path) -----
        int nzc = ((zb.y - zb.x) >> 5) + 1;
        float pzc[3];
        #pragma unroll
        for (int k = 0; k < 3; ++k)
            pzc[k] = s_p[min(zb.x + k*32 + lane, 95)];
        for (int xi = ib.x; xi <= ib.y; ++xi) {
            float px  = s_p[xi];
            float e0x = fmaf(P0.x, px, P0.w);
            float e1x = fmaf(P1.x, px, P1.w);
            float e2x = fmaf(P2.x, px, P2.w);
            int rowx = xi * G_;
            for (int yi = ib.z + warp; yi <= ib.w; yi += 16) {
                float py = s_p[yi];
                float e0 = fmaf(P0.y, py, e0x);
                float e1 = fmaf(P1.y, py, e1x);
                float e2 = fmaf(P2.y, py, e2x);
                float* col = outb + (size_t)(rowx + yi) * G_ + zb.x + lane;
                #pragma unroll
                for (int k = 0; k < 3; ++k) {
                    if (k >= nzc) break;
                    float l0 = fmaf(P0.z, pzc[k], e0);
                    float l1 = fmaf(P1.z, pzc[k], e1);
                    float l2 = fmaf(P2.z, pzc[k], e2);
                    float l3 = 1.0f - (l0 + l1 + l2);
                    float m = fminf(fminf(l0, l1), fminf(l2, l3));
                    int z = zb.x + k*32 + lane;
                    if ((m >= 0.0f) && (z <= zb.y)) col[k*32] = 1.0f;
                }
            }
        }
        return;
    }

    // -------- fast path --------
    float4 W = T.w;
    bool s0 = P0.z > 0.0f, s1 = P1.z > 0.0f, s2 = P2.z > 0.0f;
    bool s3 = (-(P0.z + P1.z + P2.z)) > 0.0f;   // sign of n3z

    for (int xi = ib.x + warp; xi <= ib.y; xi += 16) {
        float px  = s_p[xi];
        float ex0 = fmaf(P0.x, px, P0.w);
        float ex1 = fmaf(P1.x, px, P1.w);
        float ex2 = fmaf(P2.x, px, P2.w);

        for (int ybase = ib.z; ybase <= ib.w; ybase += 32) {
            int  y   = ybase + lane;
            bool yok = (y <= ib.w);
            float py = s_p[y > 95 ? 95 : y];
            float e0 = fmaf(P0.y, py, ex0);
            float e1 = fmaf(P1.y, py, ex1);
            float e2 = fmaf(P2.y, py, ex2);
            float e3 = 1.0f - (e0 + e1 + e2);   // approx linear const, plane 3

            // approximate crossing positions in z-index space
            float i0 = fmaf(e0, W.x, 47.5f);
            float i1 = fmaf(e1, W.y, 47.5f);
            float i2 = fmaf(e2, W.z, 47.5f);
            float i3 = fmaf(e3, W.w, 47.5f);
            float lo = fmaxf(fmaxf(s0 ? i0 : -1e30f, s1 ? i1 : -1e30f),
                             fmaxf(s2 ? i2 : -1e30f, s3 ? i3 : -1e30f));
            float hi = fminf(fminf(s0 ? 1e30f : i0, s1 ? 1e30f : i1),
                             fminf(s2 ? 1e30f : i2, s3 ? 1e30f : i3));
            int sA = __float2int_ru(lo);
            int eA = __float2int_rd(hi);

            int st = 96, en = 0;                // empty encoding: st > en
            bool act = yok && (sA <= eA + 2);   // crossing err < 0.25 => safe skip
            if (__any_sync(0xffffffffu, act)) {
                // exact membership test — IDENTICAL FP chain to the passing kernel
                auto TST = [&](int z) -> bool {
                    float pz = s_p[z];
                    float l0 = fmaf(P0.z, pz, e0);
                    float l1 = fmaf(P1.z, pz, e1);
                    float l2 = fmaf(P2.z, pz, e2);
                    float l3 = 1.0f - (l0 + l1 + l2);
                    return fminf(fminf(l0, l1), fminf(l2, l3)) >= 0.0f;
                };
                if (act) {
                    // clamp-once: candidates {c-1, c, c+1} with c in [1,94].
                    // Equivalent to per-candidate clamping under the act-margin
                    // invariant (true run start/end within +/-1 of sA/eA).
                    int sc = min(max(sA, 1), 94);
                    bool t0 = TST(sc-1), t1 = TST(sc), t2 = TST(sc+1);
                    int stc = t0 ? sc-1 : (t1 ? sc : (t2 ? sc+1 : 96));
                    int ec = min(max(eA, 1), 94);
                    bool u0 = TST(ec+1), u1 = TST(ec), u2 = TST(ec-1);
                    int enc = u0 ? ec+1 : (u1 ? ec : (u2 ? ec-1 : -1));
                    if (stc <= enc) { st = stc; en = enc; }
                }
            }

            // ---- phase 3: up to 3 flat predicated passes (z offsets 0/32/64),
            // each trimmed to [ffs(mask), 31-clz(mask)] (warp-uniform bounds).
            int len = en - st;                           // < 0 when empty
            unsigned m1 = __ballot_sync(0xffffffffu, len >= 0);
            if (m1) {
                int pk = (st << 8) | en;                 // st in [0,96], en in [0,95]
                float* base = outb + (size_t)(xi * G_ + ybase) * G_;

                int lo1 = __ffs(m1) - 1, hi1 = 31 - __clz(m1);
                #pragma unroll
                for (int jj = 0; jj < 32; ++jj) {
                    int j = lo1 + jj;
                    if (j > hi1) break;                  // warp-uniform break
                    int pkj = __shfl_sync(0xffffffffu, pk, j);
                    int bs = pkj >> 8, be = pkj & 255;
                    int zz = bs + lane;
                    if (zz <= be) base[j * G_ + zz] = 1.0f;
                }
                unsigned m2 = __ballot_sync(0xffffffffu, len >= 32);
                if (m2) {
                    int lo2 = __ffs(m2) - 1, hi2 = 31 - __clz(m2);
                    #pragma unroll
                    for (int jj = 0; jj < 32; ++jj) {
                        int j = lo2 + jj;
                        if (j > hi2) break;
                        int pkj = __shfl_sync(0xffffffffu, pk, j);
                        int bs = pkj >> 8, be = pkj & 255;
                        int zz = bs + 32 + lane;
                        if (zz <= be) base[j * G_ + zz] = 1.0f;
                    }
                }
                unsigned m3 = __ballot_sync(0xffffffffu, len >= 64);
                if (m3) {                                // len <= 95: 3 passes cover all
                    int lo3 = __ffs(m3) - 1, hi3 = 31 - __clz(m3);
                    #pragma unroll
                    for (int jj = 0; jj < 32; ++jj) {
                        int j = lo3 + jj;
                        if (j > hi3) break;
                        int pkj = __shfl_sync(0xffffffffu, pk, j);
                        int bs = pkj >> 8, be = pkj & 255;
                        int zz = bs + 64 + lane;
                        if (zz <= be) base[j * G_ + zz] = 1.0f;
                    }
                }
            }
        }
    }
}

// ---------------- launch ----------------
extern "C" void kernel_launch(void* const* d_in, const int* in_sizes, int n_in,
                              void* d_out, int out_size) {
    const float* verts = (const float*)d_in[0];
    const void*  fac   = d_in[1];
    (void)in_sizes; (void)n_in; (void)out_size;

    zero_k  <<<(B_*VOX_/4) / 256, 256>>>((float4*)d_out);
    detect_k<<<1, 256>>>((const unsigned long long*)fac);
    prep_k  <<<(B_*NF_ + 255) / 256, 256>>>(verts, fac);
    vox_k   <<<dim3(NF_, B_), 512>>>((float*)d_out);
}

// round 15
// speedup vs baseline: 2.5383x; 1.0143x over previous
#include <cuda_runtime.h>

#define B_   8
#define NV_  2048
#define NF_  512
#define G_   96
#define VOX_ (G_*G_*G_)   // 884736
#define XSPLIT_ 2

// ---------------- scratch (no allocation allowed) ----------------
struct Tet {
    float4 p0, p1, p2;   // plane r: (nx,ny,nz,c), lambda_r = nx*px+ny*py+nz*pz+c
    float4 w;            // per-plane -48/nz (x,y,z -> planes 0..2, w -> plane 3)
    int4   ib;           // xlo,xhi,ylo,yhi  (voxel index AABB, +1 guard)
    int2   zb;           // zlo,zhi
    int    flags;        // 0 = degenerate skip, 1 = fast path, 2 = fallback
    int    pad;
};
static __device__ Tet g_t[B_*NF_];
static __device__ int g_is32;

// ---------------- 0) output zero-fill ----------------
__global__ void zero_k(float4* __restrict__ o) {
    o[blockIdx.x * 256 + threadIdx.x] = make_float4(0.f, 0.f, 0.f, 0.f);
}

// ---------------- 1) facet dtype sniff (int64 vs silently-demoted int32) ---
__global__ void detect_k(const unsigned long long* __restrict__ f) {
    int any = 0;
    for (int idx = threadIdx.x; idx < B_*NF_*2; idx += blockDim.x)
        if (f[idx] >= (unsigned long long)NV_) any = 1;
    any = __syncthreads_or(any);
    if (threadIdx.x == 0) g_is32 = any;
}

// ---------------- 2) per-tet precompute ----------------
__device__ __forceinline__ bool ill_cond(float nx, float ny, float nz, float c) {
    float M = fmaxf(fmaxf(fabsf(nx), fabsf(ny)), fmaxf(fabsf(c), 1.0f));
    return 1e4f * fabsf(nz) < M;   // crossing-index error could exceed ~0.25 voxel
}

__global__ void prep_k(const float* __restrict__ verts, const void* __restrict__ fac) {
    int t = blockIdx.x * blockDim.x + threadIdx.x;
    if (t >= B_*NF_) return;
    int b = t >> 9;

    int i0, i1, i2, i3;
    if (g_is32) {
        const int* p = (const int*)fac + t*4;
        i0 = p[0]; i1 = p[1]; i2 = p[2]; i3 = p[3];
    } else {
        const long long* p = (const long long*)fac + t*4;
        i0 = (int)p[0]; i1 = (int)p[1]; i2 = (int)p[2]; i3 = (int)p[3];
    }

    const float* vb = verts + b * (NV_*3);
    float x0 = vb[3*i0+0], y0 = vb[3*i0+1], z0 = vb[3*i0+2];
    float x1 = vb[3*i1+0], y1 = vb[3*i1+1], z1 = vb[3*i1+2];
    float x2 = vb[3*i2+0], y2 = vb[3*i2+1], z2 = vb[3*i2+2];
    float x3 = vb[3*i3+0], y3 = vb[3*i3+1], z3 = vb[3*i3+2];

    float ca = x0-x3, cb = x1-x3, cc = x2-x3;
    float cd = y0-y3, ce = y1-y3, cf = y2-y3;
    float cg = z0-z3, ch = z1-z3, ci = z2-z3;

    // adjugate + det, uncontracted to mirror the reference
    float a00 = __fsub_rn(__fmul_rn(ce,ci), __fmul_rn(cf,ch));
    float a01 = __fsub_rn(__fmul_rn(cc,ch), __fmul_rn(cb,ci));
    float a02 = __fsub_rn(__fmul_rn(cb,cf), __fmul_rn(cc,ce));
    float a10 = __fsub_rn(__fmul_rn(cf,cg), __fmul_rn(cd,ci));
    float a11 = __fsub_rn(__fmul_rn(ca,ci), __fmul_rn(cc,cg));
    float a12 = __fsub_rn(__fmul_rn(cc,cd), __fmul_rn(ca,cf));
    float a20 = __fsub_rn(__fmul_rn(cd,ch), __fmul_rn(ce,cg));
    float a21 = __fsub_rn(__fmul_rn(cb,cg), __fmul_rn(ca,ch));
    float a22 = __fsub_rn(__fmul_rn(ca,ce), __fmul_rn(cb,cd));
    float u   = __fsub_rn(__fmul_rn(cd,ci), __fmul_rn(cf,cg));
    float det = __fadd_rn(__fsub_rn(__fmul_rn(ca,a00), __fmul_rn(cb,u)),
                          __fmul_rn(cc,a20));

    double inv = 1.0 / (double)det;
    float4 p0, p1, p2;
    p0.x = (float)((double)a00*inv); p0.y = (float)((double)a01*inv); p0.z = (float)((double)a02*inv);
    p1.x = (float)((double)a10*inv); p1.y = (float)((double)a11*inv); p1.z = (float)((double)a12*inv);
    p2.x = (float)((double)a20*inv); p2.y = (float)((double)a21*inv); p2.z = (float)((double)a22*inv);
    p0.w = (float)(-((double)a00*x3 + (double)a01*y3 + (double)a02*z3) * inv);
    p1.w = (float)(-((double)a10*x3 + (double)a11*y3 + (double)a12*z3) * inv);
    p2.w = (float)(-((double)a20*x3 + (double)a21*y3 + (double)a22*z3) * inv);

    // plane 3 (l3 = 1 - l0 - l1 - l2) linear-form coefficients (approx use only)
    float n3x = -(p0.x + p1.x + p2.x);
    float n3y = -(p0.y + p1.y + p2.y);
    float n3z = -(p0.z + p1.z + p2.z);
    float c3  = 1.0f - (p0.w + p1.w + p2.w);

    const float M = 1e-5f;  // conservative AABB margin
    float bxmin = fminf(fminf(x0,x1), fminf(x2,x3)) - M;
    float bxmax = fmaxf(fmaxf(x0,x1), fmaxf(x2,x3)) + M;
    float bymin = fminf(fminf(y0,y1), fminf(y2,y3)) - M;
    float bymax = fmaxf(fmaxf(y0,y1), fmaxf(y2,y3)) + M;
    float bzmin = fminf(fminf(z0,z1), fminf(z2,z3)) - M;
    float bzmax = fmaxf(fmaxf(z0,z1), fmaxf(z2,z3)) + M;

    Tet T;
    T.ib.x = max(0,  (int)ceilf ((96.f*bxmin + 95.f)*0.5f) - 1);
    T.ib.y = min(95, (int)floorf((96.f*bxmax + 95.f)*0.5f) + 1);
    T.ib.z = max(0,  (int)ceilf ((96.f*bymin + 95.f)*0.5f) - 1);
    T.ib.w = min(95, (int)floorf((96.f*bymax + 95.f)*0.5f) + 1);
    T.zb.x = max(0,  (int)ceilf ((96.f*bzmin + 95.f)*0.5f) - 1);
    T.zb.y = min(95, (int)floorf((96.f*bzmax + 95.f)*0.5f) + 1);

    int flags;
    if (!(fabsf(det) > 0.0f)) flags = 0;                 // degenerate -> never inside
    else if (ill_cond(p0.x,p0.y,p0.z,p0.w) || ill_cond(p1.x,p1.y,p1.z,p1.w) ||
             ill_cond(p2.x,p2.y,p2.z,p2.w) || ill_cond(n3x,n3y,n3z,c3))
        flags = 2;                                       // rare: exact chunked path
    else flags = 1;

    float4 w;
    w.x = (float)(-48.0 / (double)p0.z);
    w.y = (float)(-48.0 / (double)p1.z);
    w.z = (float)(-48.0 / (double)p2.z);
    w.w = (float)(-48.0 / (double)n3z);

    T.p0 = p0; T.p1 = p1; T.p2 = p2; T.w = w; T.flags = flags; T.pad = 0;
    g_t[t] = T;
}

// ---------------- 3) per-tet rasterize: exact z-run per column ------------
// block = half a tet (x-split x2); 8 warps stride x rows within the half;
// lanes = 32 y-columns per chunk.
__global__ __launch_bounds__(256) void vox_k(float* __restrict__ out) {
    __shared__ float s_p[128];          // padded: [96,128) safe finite values
    if (threadIdx.x < 128) {
        int zi = threadIdx.x < G_ ? (int)threadIdx.x : 95;
        s_p[threadIdx.x] = __fdiv_rn((float)(2*zi - 95), 96.0f);
    }
    __syncthreads();

    int tet  = blockIdx.x >> 1;
    int half = blockIdx.x & 1;
    const Tet& T = g_t[blockIdx.y * NF_ + tet];
    int flags = T.flags;
    if (flags == 0) return;

    int warp = threadIdx.x >> 5, lane = threadIdx.x & 31;
    float4 P0 = T.p0, P1 = T.p1, P2 = T.p2;
    int4 ib = T.ib;
    float* outb = out + (size_t)blockIdx.y * VOX_;

    // x-split: half 0 = [ib.x, ib.x+xh-1], half 1 = [ib.x+xh, ib.y]
    int nx = ib.y - ib.x + 1;
    int xh = (nx + 1) >> 1;
    int xlo = ib.x + half * xh;
    int xhi = half ? ib.y : (ib.x + xh - 1);

    if (flags == 2) {
        // -------- fallback: exact chunked test over box half (R4 path) ------
        int2 zb = T.zb;
        int nzc = ((zb.y - zb.x) >> 5) + 1;
        float pzc[3];
        #pragma unroll
        for (int k = 0; k < 3; ++k)
            pzc[k] = s_p[min(zb.x + k*32 + lane, 95)];
        for (int xi = xlo; xi <= xhi; ++xi) {
            float px  = s_p[xi];
            float e0x = fmaf(P0.x, px, P0.w);
            float e1x = fmaf(P1.x, px, P1.w);
            float e2x = fmaf(P2.x, px, P2.w);
            int rowx = xi * G_;
            for (int yi = ib.z + warp; yi <= ib.w; yi += 8) {
                float py = s_p[yi];
                float e0 = fmaf(P0.y, py, e0x);
                float e1 = fmaf(P1.y, py, e1x);
                float e2 = fmaf(P2.y, py, e2x);
                float* col = outb + (size_t)(rowx + yi) * G_ + zb.x + lane;
                #pragma unroll
                for (int k = 0; k < 3; ++k) {
                    if (k >= nzc) break;
                    float l0 = fmaf(P0.z, pzc[k], e0);
                    float l1 = fmaf(P1.z, pzc[k], e1);
                    float l2 = fmaf(P2.z, pzc[k], e2);
                    float l3 = 1.0f - (l0 + l1 + l2);
                    float m = fminf(fminf(l0, l1), fminf(l2, l3));
                    int z = zb.x + k*32 + lane;
                    if ((m >= 0.0f) && (z <= zb.y)) col[k*32] = 1.0f;
                }
            }
        }
        return;
    }

    // -------- fast path --------
    float4 W = T.w;
    bool s0 = P0.z > 0.0f, s1 = P1.z > 0.0f, s2 = P2.z > 0.0f;
    bool s3 = (-(P0.z + P1.z + P2.z)) > 0.0f;   // sign of n3z

    for (int xi = xlo + warp; xi <= xhi; xi += 8) {
        float px  = s_p[xi];
        float ex0 = fmaf(P0.x, px, P0.w);
        float ex1 = fmaf(P1.x, px, P1.w);
        float ex2 = fmaf(P2.x, px, P2.w);

        for (int ybase = ib.z; ybase <= ib.w; ybase += 32) {
            int  y   = ybase + lane;
            bool yok = (y <= ib.w);
            float py = s_p[y];                  // padded LUT: no clamp needed
            float e0 = fmaf(P0.y, py, ex0);
            float e1 = fmaf(P1.y, py, ex1);
            float e2 = fmaf(P2.y, py, ex2);
            float e3 = 1.0f - (e0 + e1 + e2);   // approx linear const, plane 3

            // approximate crossing positions in z-index space
            float i0 = fmaf(e0, W.x, 47.5f);
            float i1 = fmaf(e1, W.y, 47.5f);
            float i2 = fmaf(e2, W.z, 47.5f);
            float i3 = fmaf(e3, W.w, 47.5f);
            float lo = fmaxf(fmaxf(s0 ? i0 : -1e30f, s1 ? i1 : -1e30f),
                             fmaxf(s2 ? i2 : -1e30f, s3 ? i3 : -1e30f));
            float hi = fminf(fminf(s0 ? 1e30f : i0, s1 ? 1e30f : i1),
                             fminf(s2 ? 1e30f : i2, s3 ? 1e30f : i3));
            int sA = __float2int_ru(lo);
            int eA = __float2int_rd(hi);

            int st = 96, en = 0;                // empty encoding: st > en
            bool act = yok && (sA <= eA + 2);   // crossing err < 0.25 => safe skip
            if (__any_sync(0xffffffffu, act)) {
                // exact membership test — IDENTICAL FP chain to the passing kernel
                auto TST = [&](int z) -> bool {
                    float pz = s_p[z];
                    float l0 = fmaf(P0.z, pz, e0);
                    float l1 = fmaf(P1.z, pz, e1);
                    float l2 = fmaf(P2.z, pz, e2);
                    float l3 = 1.0f - (l0 + l1 + l2);
                    return fminf(fminf(l0, l1), fminf(l2, l3)) >= 0.0f;
                };
                if (act) {
                    // clamp-once: candidates {c-1, c, c+1} with c in [1,94]
                    int sc = min(max(sA, 1), 94);
                    bool t0 = TST(sc-1), t1 = TST(sc), t2 = TST(sc+1);
                    int stc = t0 ? sc-1 : (t1 ? sc : (t2 ? sc+1 : 96));
                    int ec = min(max(eA, 1), 94);
                    bool u0 = TST(ec+1), u1 = TST(ec), u2 = TST(ec-1);
                    int enc = u0 ? ec+1 : (u1 ? ec : (u2 ? ec-1 : -1));
                    if (stc <= enc) { st = stc; en = enc; }
                }
            }

            // ---- phase 3: up to 3 flat predicated passes (z offsets 0/32/64),
            // each trimmed to [ffs(mask), 31-clz(mask)] (warp-uniform bounds).
            int len = en - st;                           // < 0 when empty
            unsigned m1 = __ballot_sync(0xffffffffu, len >= 0);
            if (m1) {
                int pk = (st << 8) | en;                 // st in [0,96], en in [0,95]
                float* base = outb + (size_t)(xi * G_ + ybase) * G_;

                int lo1 = __ffs(m1) - 1, hi1 = 31 - __clz(m1);
                #pragma unroll
                for (int jj = 0; jj < 32; ++jj) {
                    int j = lo1 + jj;
                    if (j > hi1) break;                  // warp-uniform break
                    int pkj = __shfl_sync(0xffffffffu, pk, j);
                    int bs = pkj >> 8, be = pkj & 255;
                    int zz = bs + lane;
                    if (zz <= be) base[j * G_ + zz] = 1.0f;
                }
                unsigned m2 = __ballot_sync(0xffffffffu, len >= 32);
                if (m2) {
                    int lo2 = __ffs(m2) - 1, hi2 = 31 - __clz(m2);
                    #pragma unroll
                    for (int jj = 0; jj < 32; ++jj) {
                        int j = lo2 + jj;
                        if (j > hi2) break;
                        int pkj = __shfl_sync(0xffffffffu, pk, j);
                        int bs = pkj >> 8, be = pkj & 255;
                        int zz = bs + 32 + lane;
                        if (zz <= be) base[j * G_ + zz] = 1.0f;
                    }
                }
                unsigned m3 = __ballot_sync(0xffffffffu, len >= 64);
                if (m3) {                                // len <= 95: 3 passes cover all
                    int lo3 = __ffs(m3) - 1, hi3 = 31 - __clz(m3);
                    #pragma unroll
                    for (int jj = 0; jj < 32; ++jj) {
                        int j = lo3 + jj;
                        if (j > hi3) break;
                        int pkj = __shfl_sync(0xffffffffu, pk, j);
                        int bs = pkj >> 8, be = pkj & 255;
                        int zz = bs + 64 + lane;
                        if (zz <= be) base[j * G_ + zz] = 1.0f;
                    }
                }
            }
        }
    }
}

// ---------------- launch ----------------
extern "C" void kernel_launch(void* const* d_in, const int* in_sizes, int n_in,
                              void* d_out, int out_size) {
    const float* verts = (const float*)d_in[0];
    const void*  fac   = d_in[1];
    (void)in_sizes; (void)n_in; (void)out_size;

    zero_k  <<<(B_*VOX_/4) / 256, 256>>>((float4*)d_out);
    detect_k<<<1, 256>>>((const unsigned long long*)fac);
    prep_k  <<<(B_*NF_ + 255) / 256, 256>>>(verts, fac);
    vox_k   <<<dim3(NF_*XSPLIT_, B_), 256>>>((float*)d_out);
}